// round 4
// baseline (speedup 1.0000x reference)
#include <cuda_runtime.h>

#define IN_F   4096
#define OUT_F  4096
#define RANK   8
#define MAX_TOKENS 8192

// t duplicated as (t,t) 64-bit pairs so stage2 can FFMA2 straight from smem.
__device__ float2 g_t2[MAX_TOKENS * RANK];   // 512 KB

// ---- packed f32x2 helpers (ptxas never auto-fuses; PTX-only path) ----------
__device__ __forceinline__ unsigned long long fma2(unsigned long long a,
                                                   unsigned long long b,
                                                   unsigned long long c) {
    unsigned long long d;
    asm("fma.rn.f32x2 %0, %1, %2, %3;" : "=l"(d) : "l"(a), "l"(b), "l"(c));
    return d;
}
__device__ __forceinline__ float2 unpack2(unsigned long long v) {
    float2 f;
    asm("mov.b64 {%0, %1}, %2;" : "=f"(f.x), "=f"(f.y) : "l"(v));
    return f;
}
__device__ __forceinline__ unsigned long long pack2(float a, float b) {
    unsigned long long v;
    asm("mov.b64 %0, {%1, %2};" : "=l"(v) : "f"(a), "f"(b));
    return v;
}

// ---------------------------------------------------------------------------
// Stage 1: t[tok, r] = sum_i x[tok, i] * core1[r, i]
// 128 threads = 4 warps, 4 tokens per warp (core1 L1 traffic amortized 4x),
// full IN_F row per warp. x and c1 loaded as ulonglong2 so each 64-bit half
// of the LDG.128 is directly an f32x2 operand: 64 FFMA2/iter vs 128 FFMA.
// 512 blocks @ ~4/SM = one clean wave.
// ---------------------------------------------------------------------------
__global__ void __launch_bounds__(128) tt_stage1(const float* __restrict__ x,
                                                 const float* __restrict__ c1) {
    const int warp = threadIdx.x >> 5;
    const int lane = threadIdx.x & 31;
    const int token0 = (blockIdx.x * 4 + warp) * 4;

    const ulonglong2* xp = reinterpret_cast<const ulonglong2*>(x)
                         + (size_t)token0 * (IN_F / 4);
    const ulonglong2* cp = reinterpret_cast<const ulonglong2*>(c1);

    unsigned long long acc[4][RANK];
#pragma unroll
    for (int t = 0; t < 4; t++)
#pragma unroll
        for (int r = 0; r < RANK; r++) acc[t][r] = 0ull;   // bits of (0.f,0.f)

#pragma unroll 2
    for (int i = lane; i < IN_F / 4; i += 32) {
        ulonglong2 xv[4];
#pragma unroll
        for (int t = 0; t < 4; t++)
            xv[t] = __ldcs(xp + (size_t)t * (IN_F / 4) + i);   // stream x
#pragma unroll
        for (int r = 0; r < RANK; r++) {
            const ulonglong2 c = __ldg(cp + (size_t)r * (IN_F / 4) + i);
#pragma unroll
            for (int t = 0; t < 4; t++) {
                acc[t][r] = fma2(xv[t].x, c.x, acc[t][r]);
                acc[t][r] = fma2(xv[t].y, c.y, acc[t][r]);
            }
        }
    }

#pragma unroll
    for (int t = 0; t < 4; t++)
#pragma unroll
        for (int r = 0; r < RANK; r++) {
            const float2 f = unpack2(acc[t][r]);
            float v = f.x + f.y;
#pragma unroll
            for (int off = 16; off; off >>= 1)
                v += __shfl_xor_sync(0xffffffffu, v, off);
            if (lane == 0)
                g_t2[(size_t)(token0 + t) * RANK + r] = make_float2(v, v);
        }
}

// ---------------------------------------------------------------------------
// Stage 2: y[tok, o] = bias[o] + sum_r t[tok, r] * core0[o, r]
// Thread owns 4 consecutive outputs. Coefficients pre-packed once into
// f32x2 pairs (c0[o][r], c0[o+1][r]); t pairs (t,t) broadcast from smem.
// Token loop: 8 LDS.64 + 16 FFMA2 + 1 STG.128  (was 8 LDS + 32 FFMA + STG).
// ---------------------------------------------------------------------------
__global__ void __launch_bounds__(256) tt_stage2(const float* __restrict__ c0,
                                                 const float* __restrict__ bias,
                                                 float* __restrict__ y) {
    __shared__ unsigned long long ts[32 * RANK];   // (t,t) pairs, 2 KB
    const int tid = threadIdx.x;
    const int token0 = blockIdx.y * 32;
    const int o = blockIdx.x * 1024 + tid * 4;

    ts[tid] = reinterpret_cast<const unsigned long long*>(g_t2)
                  [(size_t)token0 * RANK + tid];

    // Load 4 rows of core0 (8 floats each) and pre-pack output-pair coeffs.
    float4 ca[4], cb[4];
#pragma unroll
    for (int j = 0; j < 4; j++) {
        const float4* c = reinterpret_cast<const float4*>(c0 + (size_t)(o + j) * RANK);
        ca[j] = __ldg(c);
        cb[j] = __ldg(c + 1);
    }
    unsigned long long cp01[RANK], cp23[RANK];
    cp01[0] = pack2(ca[0].x, ca[1].x);  cp23[0] = pack2(ca[2].x, ca[3].x);
    cp01[1] = pack2(ca[0].y, ca[1].y);  cp23[1] = pack2(ca[2].y, ca[3].y);
    cp01[2] = pack2(ca[0].z, ca[1].z);  cp23[2] = pack2(ca[2].z, ca[3].z);
    cp01[3] = pack2(ca[0].w, ca[1].w);  cp23[3] = pack2(ca[2].w, ca[3].w);
    cp01[4] = pack2(cb[0].x, cb[1].x);  cp23[4] = pack2(cb[2].x, cb[3].x);
    cp01[5] = pack2(cb[0].y, cb[1].y);  cp23[5] = pack2(cb[2].y, cb[3].y);
    cp01[6] = pack2(cb[0].z, cb[1].z);  cp23[6] = pack2(cb[2].z, cb[3].z);
    cp01[7] = pack2(cb[0].w, cb[1].w);  cp23[7] = pack2(cb[2].w, cb[3].w);

    const float4 bv = __ldg(reinterpret_cast<const float4*>(bias + o));
    const unsigned long long b01 = pack2(bv.x, bv.y);
    const unsigned long long b23 = pack2(bv.z, bv.w);

    __syncthreads();

#pragma unroll 4
    for (int tok = 0; tok < 32; tok++) {
        const unsigned long long* tr = &ts[tok * RANK];
        unsigned long long r01 = b01, r23 = b23;
#pragma unroll
        for (int r = 0; r < RANK; r++) {
            const unsigned long long tv = tr[r];
            r01 = fma2(cp01[r], tv, r01);
            r23 = fma2(cp23[r], tv, r23);
        }
        const float2 f01 = unpack2(r01);
        const float2 f23 = unpack2(r23);
        const float4 res = make_float4(f01.x, f01.y, f23.x, f23.y);
        *reinterpret_cast<float4*>(y + (size_t)(token0 + tok) * OUT_F + o) = res;
    }
}

extern "C" void kernel_launch(void* const* d_in, const int* in_sizes, int n_in,
                              void* d_out, int out_size) {
    const float* x    = (const float*)d_in[0];   // [TOKENS, IN_F]
    const float* c0   = (const float*)d_in[1];   // [OUT_F, RANK]
    const float* c1   = (const float*)d_in[2];   // [RANK, IN_F]
    const float* bias = (const float*)d_in[3];   // [OUT_F]
    float* y = (float*)d_out;

    const int tokens = in_sizes[0] / IN_F;       // 8192

    // Stage 1: 16 tokens/block (4 warps x 4 tokens), 512 blocks
    tt_stage1<<<tokens / 16, 128>>>(x, c1);

    // Stage 2: 4 output chunks x 32-token groups = 1024 blocks
    dim3 g2(OUT_F / 1024, tokens / 32);
    tt_stage2<<<g2, 256>>>(c0, bias, y);
}